// round 2
// baseline (speedup 1.0000x reference)
#include <cuda_runtime.h>
#include <math.h>

// ---------------------------------------------------------------------------
// Problem constants
// ---------------------------------------------------------------------------
#define BATCH   8
#define SEQ     2048
#define DIM     512
#define NTOK    (BATCH * SEQ)          // 16384

// GEMM tiling
#define BM 128
#define BN 128
#define BK 16
#define NTHREADS 256

// Epilogue tags
#define EPI_GATE     0
#define EPI_SCALE    1
#define EPI_ADD      2
#define EPI_GELU     3
#define EPI_BIAS_RES 4

// ---------------------------------------------------------------------------
// Scratch (device globals: allocation-free rule)
// ---------------------------------------------------------------------------
__device__ float g_comb  [(size_t)NTOK * 2 * DIM];     // 64 MB  [16384,1024]
__device__ float g_fused [(size_t)NTOK * DIM];         // 32 MB  [16384,512]
__device__ float g_scores[(size_t)BATCH * SEQ * SEQ];  // 128 MB [8,2048,2048]
__device__ float g_q     [(size_t)NTOK * DIM];         // 32 MB
__device__ float g_h     [(size_t)NTOK * 2 * DIM];     // 64 MB
__device__ float g_y     [(size_t)NTOK * DIM];         // 32 MB

// ---------------------------------------------------------------------------
// Warp helpers
// ---------------------------------------------------------------------------
__device__ __forceinline__ float warpMax(float v) {
    #pragma unroll
    for (int o = 16; o > 0; o >>= 1) v = fmaxf(v, __shfl_xor_sync(0xffffffffu, v, o));
    return v;
}
__device__ __forceinline__ float warpSum(float v) {
    #pragma unroll
    for (int o = 16; o > 0; o >>= 1) v += __shfl_xor_sync(0xffffffffu, v, o);
    return v;
}

// ---------------------------------------------------------------------------
// Tiled fp32 GEMM: C[M,N] = A[M,K] * B  (B is [K,N] if !TB, [N,K] if TB)
// 128x128x16 tile, 256 threads, 8x8 micro-tile per thread.
// All dims assumed multiples of the tile sizes (true for this problem).
// ---------------------------------------------------------------------------
template<int EPI, bool TB>
__global__ void __launch_bounds__(NTHREADS)
gemm_kernel(const float* __restrict__ A, const float* __restrict__ B,
            float* __restrict__ C,
            int M, int N, int K, int lda, int ldb, int ldc,
            size_t sA, size_t sB, size_t sC,
            const float* __restrict__ bias,
            const float* __restrict__ res0,
            const float* __restrict__ res1,
            float scale)
{
    __shared__ float As[BK][BM];
    __shared__ float Bs[BK][BN];

    const int z = blockIdx.z;
    A += (size_t)z * sA;
    B += (size_t)z * sB;
    C += (size_t)z * sC;
    if (res0) res0 += (size_t)z * sC;
    if (res1) res1 += (size_t)z * sC;

    const int bm  = blockIdx.y * BM;
    const int bn  = blockIdx.x * BN;
    const int tid = threadIdx.x;
    const int tx  = tid & 15;   // 0..15 -> col group
    const int ty  = tid >> 4;   // 0..15 -> row group

    float acc[8][8];
    #pragma unroll
    for (int i = 0; i < 8; i++)
        #pragma unroll
        for (int j = 0; j < 8; j++) acc[i][j] = 0.f;

    for (int kk = 0; kk < K; kk += BK) {
        // ---- load A tile (128 rows x 16 k), store transposed As[k][m]
        #pragma unroll
        for (int l = 0; l < 2; l++) {
            int idx = tid + l * NTHREADS;       // 0..511
            int r   = idx >> 2;                 // 0..127
            int c   = (idx & 3) << 2;           // 0,4,8,12
            float4 v = *reinterpret_cast<const float4*>(
                &A[(size_t)(bm + r) * lda + kk + c]);
            As[c + 0][r] = v.x; As[c + 1][r] = v.y;
            As[c + 2][r] = v.z; As[c + 3][r] = v.w;
        }
        // ---- load B tile -> Bs[k][n]
        if (TB) {
            // B is [N,K] row-major: tile 128 n-rows x 16 k-cols
            #pragma unroll
            for (int l = 0; l < 2; l++) {
                int idx = tid + l * NTHREADS;
                int r   = idx >> 2;             // n 0..127
                int c   = (idx & 3) << 2;       // k
                float4 v = *reinterpret_cast<const float4*>(
                    &B[(size_t)(bn + r) * ldb + kk + c]);
                Bs[c + 0][r] = v.x; Bs[c + 1][r] = v.y;
                Bs[c + 2][r] = v.z; Bs[c + 3][r] = v.w;
            }
        } else {
            // B is [K,N] row-major: tile 16 k-rows x 128 n-cols
            #pragma unroll
            for (int l = 0; l < 2; l++) {
                int idx = tid + l * NTHREADS;
                int r   = idx >> 5;             // k 0..15
                int c   = (idx & 31) << 2;      // n
                float4 v = *reinterpret_cast<const float4*>(
                    &B[(size_t)(kk + r) * ldb + bn + c]);
                *reinterpret_cast<float4*>(&Bs[r][c]) = v;
            }
        }
        __syncthreads();

        #pragma unroll
        for (int k = 0; k < BK; k++) {
            float a[8], b[8];
            *reinterpret_cast<float4*>(&a[0]) = *reinterpret_cast<const float4*>(&As[k][ty * 8]);
            *reinterpret_cast<float4*>(&a[4]) = *reinterpret_cast<const float4*>(&As[k][ty * 8 + 4]);
            *reinterpret_cast<float4*>(&b[0]) = *reinterpret_cast<const float4*>(&Bs[k][tx * 8]);
            *reinterpret_cast<float4*>(&b[4]) = *reinterpret_cast<const float4*>(&Bs[k][tx * 8 + 4]);
            #pragma unroll
            for (int i = 0; i < 8; i++)
                #pragma unroll
                for (int j = 0; j < 8; j++)
                    acc[i][j] = fmaf(a[i], b[j], acc[i][j]);
        }
        __syncthreads();
    }

    // ---- epilogue
    const int row0 = bm + ty * 8;
    const int col0 = bn + tx * 8;
    #pragma unroll
    for (int i = 0; i < 8; i++) {
        int r = row0 + i;
        float outv[8];
        #pragma unroll
        for (int j = 0; j < 8; j++) {
            int c = col0 + j;
            size_t g = (size_t)r * ldc + c;
            float v = acc[i][j];
            if (EPI == EPI_GATE) {
                float gt = 1.f / (1.f + expf(-(v + bias[c])));
                outv[j] = gt * res0[g] + (1.f - gt) * res1[g];
            } else if (EPI == EPI_SCALE) {
                outv[j] = v * scale;
            } else if (EPI == EPI_ADD) {
                outv[j] = v + res0[g];
            } else if (EPI == EPI_GELU) {
                float x = v + bias[c];
                outv[j] = 0.5f * x * (1.f + erff(x * 0.70710678118654752440f));
            } else { // EPI_BIAS_RES
                outv[j] = v + bias[c] + res0[g];
            }
        }
        size_t gbase = (size_t)r * ldc + col0;
        *reinterpret_cast<float4*>(&C[gbase])     = *reinterpret_cast<float4*>(&outv[0]);
        *reinterpret_cast<float4*>(&C[gbase + 4]) = *reinterpret_cast<float4*>(&outv[4]);
    }
}

// ---------------------------------------------------------------------------
// Concat along features: out[r, 0:512] = a[r,:], out[r, 512:1024] = b[r,:]
// One float4 per thread; 16384*256 float4 total.
// ---------------------------------------------------------------------------
__global__ void __launch_bounds__(256)
concat_kernel(const float* __restrict__ a, const float* __restrict__ b,
              float* __restrict__ o)
{
    size_t idx = (size_t)blockIdx.x * 256 + threadIdx.x;  // float4 index
    size_t r   = idx >> 8;        // row (1024 floats = 256 float4 per row)
    int    c4  = (int)(idx & 255);
    float4 v;
    if (c4 < 128) v = reinterpret_cast<const float4*>(a)[r * 128 + c4];
    else          v = reinterpret_cast<const float4*>(b)[r * 128 + (c4 - 128)];
    reinterpret_cast<float4*>(o)[idx] = v;
}

// ---------------------------------------------------------------------------
// Row softmax over 2048 columns, in place. One block (256 thr) per row.
// ---------------------------------------------------------------------------
__global__ void __launch_bounds__(256)
softmax_kernel(float* __restrict__ S)
{
    float* p = S + (size_t)blockIdx.x * SEQ;
    const int tid  = threadIdx.x;
    const int lane = tid & 31;
    const int wid  = tid >> 5;
    __shared__ float sh[8];

    float v[8];
    *reinterpret_cast<float4*>(&v[0]) = *reinterpret_cast<const float4*>(&p[tid * 8]);
    *reinterpret_cast<float4*>(&v[4]) = *reinterpret_cast<const float4*>(&p[tid * 8 + 4]);

    float m = v[0];
    #pragma unroll
    for (int i = 1; i < 8; i++) m = fmaxf(m, v[i]);
    m = warpMax(m);
    if (lane == 0) sh[wid] = m;
    __syncthreads();
    m = sh[0];
    #pragma unroll
    for (int w = 1; w < 8; w++) m = fmaxf(m, sh[w]);
    __syncthreads();  // done reading sh before reuse

    float s = 0.f;
    #pragma unroll
    for (int i = 0; i < 8; i++) { v[i] = expf(v[i] - m); s += v[i]; }
    s = warpSum(s);
    if (lane == 0) sh[wid] = s;
    __syncthreads();
    float tot = sh[0];
    #pragma unroll
    for (int w = 1; w < 8; w++) tot += sh[w];
    float inv = 1.f / tot;

    #pragma unroll
    for (int i = 0; i < 8; i++) v[i] *= inv;
    *reinterpret_cast<float4*>(&p[tid * 8])     = *reinterpret_cast<float4*>(&v[0]);
    *reinterpret_cast<float4*>(&p[tid * 8 + 4]) = *reinterpret_cast<float4*>(&v[4]);
}

// ---------------------------------------------------------------------------
// LayerNorm over last dim (512). One block (128 thr, 4 elems each) per row.
// ---------------------------------------------------------------------------
__global__ void __launch_bounds__(128)
layernorm_kernel(const float* __restrict__ in, float* __restrict__ out,
                 const float* __restrict__ gamma, const float* __restrict__ beta)
{
    const size_t base = (size_t)blockIdx.x * DIM;
    const int tid  = threadIdx.x;
    const int lane = tid & 31;
    const int wid  = tid >> 5;
    __shared__ float shs[4], shq[4];

    float4 x = *reinterpret_cast<const float4*>(&in[base + tid * 4]);
    float s  = x.x + x.y + x.z + x.w;
    float ss = x.x * x.x + x.y * x.y + x.z * x.z + x.w * x.w;
    s  = warpSum(s);
    ss = warpSum(ss);
    if (lane == 0) { shs[wid] = s; shq[wid] = ss; }
    __syncthreads();
    float sum = shs[0] + shs[1] + shs[2] + shs[3];
    float sq  = shq[0] + shq[1] + shq[2] + shq[3];
    float mu  = sum * (1.f / DIM);
    float var = sq * (1.f / DIM) - mu * mu;
    float rs  = rsqrtf(var + 1e-5f);

    float4 gm = *reinterpret_cast<const float4*>(&gamma[tid * 4]);
    float4 bt = *reinterpret_cast<const float4*>(&beta[tid * 4]);
    float4 o;
    o.x = (x.x - mu) * rs * gm.x + bt.x;
    o.y = (x.y - mu) * rs * gm.y + bt.y;
    o.z = (x.z - mu) * rs * gm.z + bt.z;
    o.w = (x.w - mu) * rs * gm.w + bt.w;
    *reinterpret_cast<float4*>(&out[base + tid * 4]) = o;
}

// ---------------------------------------------------------------------------
// Launch
// ---------------------------------------------------------------------------
extern "C" void kernel_launch(void* const* d_in, const int* in_sizes, int n_in,
                              void* d_out, int out_size)
{
    const float* Noise = (const float*)d_in[0];
    const float* X     = (const float*)d_in[1];
    const float* cond  = (const float*)d_in[2];
    const float* Wg    = (const float*)d_in[3];
    const float* bg    = (const float*)d_in[4];
    const float* W1    = (const float*)d_in[5];
    const float* b1    = (const float*)d_in[6];
    const float* W2    = (const float*)d_in[7];
    const float* b2    = (const float*)d_in[8];
    const float* g1    = (const float*)d_in[9];
    const float* be1   = (const float*)d_in[10];
    const float* g2    = (const float*)d_in[11];
    const float* be2   = (const float*)d_in[12];
    float* out = (float*)d_out;

    float *comb, *fused, *scores, *q, *h, *y;
    cudaGetSymbolAddress((void**)&comb,   g_comb);
    cudaGetSymbolAddress((void**)&fused,  g_fused);
    cudaGetSymbolAddress((void**)&scores, g_scores);
    cudaGetSymbolAddress((void**)&q,      g_q);
    cudaGetSymbolAddress((void**)&h,      g_h);
    cudaGetSymbolAddress((void**)&y,      g_y);

    const float scale = 0.04419417382415922f;  // 1/sqrt(512)

    // 1. combined = concat(Noise, cond)
    concat_kernel<<<NTOK, 256>>>(Noise, cond, comb);

    // 2. gate = sigmoid(combined @ Wg + bg); fused = gate*Noise + (1-gate)*cond
    gemm_kernel<EPI_GATE, false><<<dim3(DIM / BN, NTOK / BM, 1), NTHREADS>>>(
        comb, Wg, fused,
        NTOK, DIM, 2 * DIM, 2 * DIM, DIM, DIM,
        0, 0, 0, bg, Noise, cond, 0.f);

    // 3. scores = fused @ X^T * scale   (batched NT)
    gemm_kernel<EPI_SCALE, true><<<dim3(SEQ / BN, SEQ / BM, BATCH), NTHREADS>>>(
        fused, X, scores,
        SEQ, SEQ, DIM, DIM, DIM, SEQ,
        (size_t)SEQ * DIM, (size_t)SEQ * DIM, (size_t)SEQ * SEQ,
        nullptr, nullptr, nullptr, scale);

    // 4. softmax over rows (in place)
    softmax_kernel<<<NTOK, 256>>>(scores);

    // 5. fused += attn @ X   (batched NN, in place residual into fused)
    gemm_kernel<EPI_ADD, false><<<dim3(DIM / BN, SEQ / BM, BATCH), NTHREADS>>>(
        scores, X, fused,
        SEQ, DIM, SEQ, SEQ, DIM, DIM,
        (size_t)SEQ * SEQ, (size_t)SEQ * DIM, (size_t)SEQ * DIM,
        nullptr, fused, nullptr, 0.f);

    // 6. q = LN1(fused)
    layernorm_kernel<<<NTOK, 128>>>(fused, q, g1, be1);

    // 7. h = gelu(q @ W1 + b1)
    gemm_kernel<EPI_GELU, false><<<dim3(2 * DIM / BN, NTOK / BM, 1), NTHREADS>>>(
        q, W1, h,
        NTOK, 2 * DIM, DIM, DIM, 2 * DIM, 2 * DIM,
        0, 0, 0, b1, nullptr, nullptr, 0.f);

    // 8. y = h @ W2 + b2 + q
    gemm_kernel<EPI_BIAS_RES, false><<<dim3(DIM / BN, NTOK / BM, 1), NTHREADS>>>(
        h, W2, y,
        NTOK, DIM, 2 * DIM, 2 * DIM, DIM, DIM,
        0, 0, 0, b2, q, nullptr, 0.f);

    // 9. out = LN2(y)
    layernorm_kernel<<<NTOK, 128>>>(y, out, g2, be2);
}

// round 4
// speedup vs baseline: 2.8451x; 2.8451x over previous
#include <cuda_runtime.h>
#include <math.h>
#include <stdint.h>

// ---------------------------------------------------------------------------
// Problem constants
// ---------------------------------------------------------------------------
#define BATCH   8
#define SEQ     2048
#define DIM     512
#define NTOK    (BATCH * SEQ)          // 16384

// GEMM tiling (mma.sync m16n8k8 tf32)
#define BM 128
#define BN 128
#define BK 16
#define NTHREADS 256

// smem pitches (floats)
#define PA 20     // [rows][k] K-contiguous pitch (128 rows x 16 k)
#define PBN 136   // [k][n]  N-contiguous pitch  (16 k x 128 n)
#define SBUF 2560 // floats per buffer (128*20 = 2560 >= 16*136 = 2176)

// Epilogue tags
#define EPI_GATE     0
#define EPI_SCALE    1
#define EPI_ADD      2
#define EPI_GELU     3
#define EPI_BIAS_RES 4

// ---------------------------------------------------------------------------
// Scratch (device globals: allocation-free rule)
// ---------------------------------------------------------------------------
__device__ float g_comb  [(size_t)NTOK * 2 * DIM];
__device__ float g_fused [(size_t)NTOK * DIM];
__device__ float g_scores[(size_t)BATCH * SEQ * SEQ];
__device__ float g_q     [(size_t)NTOK * DIM];
__device__ float g_h     [(size_t)NTOK * 2 * DIM];
__device__ float g_y     [(size_t)NTOK * DIM];

// ---------------------------------------------------------------------------
// PTX helpers
// ---------------------------------------------------------------------------
__device__ __forceinline__ uint32_t smem_u32(const void* p) {
    uint32_t a;
    asm("{ .reg .u64 t; cvta.to.shared.u64 t, %1; cvt.u32.u64 %0, t; }" : "=r"(a) : "l"(p));
    return a;
}
__device__ __forceinline__ void cp16(uint32_t saddr, const void* gaddr) {
    asm volatile("cp.async.cg.shared.global [%0], [%1], 16;" :: "r"(saddr), "l"(gaddr));
}
__device__ __forceinline__ void cp_commit() {
    asm volatile("cp.async.commit_group;" ::: "memory");
}
__device__ __forceinline__ void cp_wait0() {
    asm volatile("cp.async.wait_group 0;" ::: "memory");
}
__device__ __forceinline__ void mma_tf32(float* c, uint32_t a0, uint32_t a1,
                                         uint32_t a2, uint32_t a3,
                                         uint32_t b0, uint32_t b1) {
    asm volatile("mma.sync.aligned.m16n8k8.row.col.f32.tf32.tf32.f32 "
                 "{%0,%1,%2,%3}, {%4,%5,%6,%7}, {%8,%9}, {%0,%1,%2,%3};"
                 : "+f"(c[0]), "+f"(c[1]), "+f"(c[2]), "+f"(c[3])
                 : "r"(a0), "r"(a1), "r"(a2), "r"(a3), "r"(b0), "r"(b1));
}
__device__ __forceinline__ uint32_t ldsf(const float* p) {
    return __float_as_uint(*p);
}

// ---------------------------------------------------------------------------
// tf32 tensor-core GEMM: C[M,N] = A[M,K] * B  (B [N,K] if TB, [K,N] if !TB)
// 128x128x16 CTA tile, 8 warps (2x4), 64x32 warp tiles, cp.async double buffer.
// ---------------------------------------------------------------------------
template<int EPI, bool TB>
__global__ void __launch_bounds__(NTHREADS)
gemm_mma(const float* __restrict__ A, const float* __restrict__ B,
         float* __restrict__ C,
         int K, int lda, int ldb, int ldc,
         size_t strA, size_t strB, size_t strC,
         const float* __restrict__ bias,
         const float* __restrict__ res0,
         const float* __restrict__ res1,
         float scale)
{
    __shared__ float As[2][SBUF];
    __shared__ float Bs[2][SBUF];

    const int z = blockIdx.z;
    A += (size_t)z * strA;
    B += (size_t)z * strB;
    C += (size_t)z * strC;
    if (res0) res0 += (size_t)z * strC;
    if (res1) res1 += (size_t)z * strC;

    const int bm   = blockIdx.y * BM;
    const int bn   = blockIdx.x * BN;
    const int tid  = threadIdx.x;
    const int wid  = tid >> 5;
    const int lane = tid & 31;
    const int warp_m = wid & 1;        // 0..1 -> 64 rows
    const int warp_n = wid >> 1;       // 0..3 -> 32 cols
    const int g  = lane >> 2;          // 0..7
    const int tg = lane & 3;           // 0..3

    const uint32_t asB = smem_u32(As);
    const uint32_t bsB = smem_u32(Bs);

    float acc[4][4][4];
    #pragma unroll
    for (int i = 0; i < 4; i++)
        #pragma unroll
        for (int j = 0; j < 4; j++)
            #pragma unroll
            for (int e = 0; e < 4; e++) acc[i][j][e] = 0.f;

    const int nit = K / BK;

    // ---- prefetch helper (2 x 16B chunks per thread per operand) ----
    auto prefetch = [&](int it) {
        const int kk  = it * BK;
        const int buf = it & 1;
        const uint32_t sa = asB + (uint32_t)buf * SBUF * 4u;
        const uint32_t sb = bsB + (uint32_t)buf * SBUF * 4u;
        #pragma unroll
        for (int t = 0; t < 2; t++) {
            int id = tid + t * NTHREADS;       // 0..511
            int r  = id >> 2;                  // 0..127
            int c4 = id & 3;
            cp16(sa + (uint32_t)(r * PA + c4 * 4) * 4u,
                 A + (size_t)(bm + r) * lda + kk + c4 * 4);
        }
        if (TB) {
            #pragma unroll
            for (int t = 0; t < 2; t++) {
                int id = tid + t * NTHREADS;
                int r  = id >> 2;              // n row 0..127
                int c4 = id & 3;
                cp16(sb + (uint32_t)(r * PA + c4 * 4) * 4u,
                     B + (size_t)(bn + r) * ldb + kk + c4 * 4);
            }
        } else {
            #pragma unroll
            for (int t = 0; t < 2; t++) {
                int id = tid + t * NTHREADS;
                int r  = id >> 5;              // k row 0..15
                int c4 = id & 31;
                cp16(sb + (uint32_t)(r * PBN + c4 * 4) * 4u,
                     B + (size_t)(kk + r) * ldb + bn + c4 * 4);
            }
        }
    };

    prefetch(0);
    cp_commit();

    for (int it = 0; it < nit; it++) {
        cp_wait0();
        __syncthreads();
        if (it + 1 < nit) { prefetch(it + 1); cp_commit(); }

        const int buf = it & 1;
        const float* Asb = As[buf];
        const float* Bsb = Bs[buf];

        #pragma unroll
        for (int ks = 0; ks < 2; ks++) {
            const int kc = ks * 8;
            uint32_t af[4][4];
            #pragma unroll
            for (int mt = 0; mt < 4; mt++) {
                int m = warp_m * 64 + mt * 16;
                const float* ap = &Asb[(m + g) * PA + kc + tg];
                af[mt][0] = ldsf(ap);
                af[mt][1] = ldsf(ap + 8 * PA);
                af[mt][2] = ldsf(ap + 4);
                af[mt][3] = ldsf(ap + 8 * PA + 4);
            }
            uint32_t bf[4][2];
            #pragma unroll
            for (int nt = 0; nt < 4; nt++) {
                int n = warp_n * 32 + nt * 8;
                if (TB) {
                    const float* bp = &Bsb[(n + g) * PA + kc + tg];
                    bf[nt][0] = ldsf(bp);
                    bf[nt][1] = ldsf(bp + 4);
                } else {
                    const float* bp = &Bsb[(kc + tg) * PBN + n + g];
                    bf[nt][0] = ldsf(bp);
                    bf[nt][1] = ldsf(bp + 4 * PBN);
                }
            }
            #pragma unroll
            for (int mt = 0; mt < 4; mt++)
                #pragma unroll
                for (int nt = 0; nt < 4; nt++)
                    mma_tf32(acc[mt][nt], af[mt][0], af[mt][1], af[mt][2], af[mt][3],
                             bf[nt][0], bf[nt][1]);
        }
        __syncthreads();
    }

    // ---- epilogue ----
    #pragma unroll
    for (int mt = 0; mt < 4; mt++) {
        #pragma unroll
        for (int nt = 0; nt < 4; nt++) {
            int r0 = bm + warp_m * 64 + mt * 16 + g;
            int cc = bn + warp_n * 32 + nt * 8 + tg * 2;
            #pragma unroll
            for (int half = 0; half < 2; half++) {
                int r = r0 + half * 8;
                float v0 = acc[mt][nt][half * 2 + 0];
                float v1 = acc[mt][nt][half * 2 + 1];
                size_t gix = (size_t)r * ldc + cc;
                float o0, o1;
                if (EPI == EPI_GATE) {
                    float gt0 = 1.f / (1.f + expf(-(v0 + bias[cc])));
                    float gt1 = 1.f / (1.f + expf(-(v1 + bias[cc + 1])));
                    o0 = gt0 * res0[gix]     + (1.f - gt0) * res1[gix];
                    o1 = gt1 * res0[gix + 1] + (1.f - gt1) * res1[gix + 1];
                } else if (EPI == EPI_SCALE) {
                    o0 = v0 * scale; o1 = v1 * scale;
                } else if (EPI == EPI_ADD) {
                    o0 = v0 + res0[gix]; o1 = v1 + res0[gix + 1];
                } else if (EPI == EPI_GELU) {
                    float x0 = v0 + bias[cc], x1 = v1 + bias[cc + 1];
                    o0 = 0.5f * x0 * (1.f + erff(x0 * 0.70710678118654752440f));
                    o1 = 0.5f * x1 * (1.f + erff(x1 * 0.70710678118654752440f));
                } else { // EPI_BIAS_RES
                    o0 = v0 + bias[cc]     + res0[gix];
                    o1 = v1 + bias[cc + 1] + res0[gix + 1];
                }
                *reinterpret_cast<float2*>(&C[gix]) = make_float2(o0, o1);
            }
        }
    }
}

// ---------------------------------------------------------------------------
// Warp helpers
// ---------------------------------------------------------------------------
__device__ __forceinline__ float warpMax(float v) {
    #pragma unroll
    for (int o = 16; o > 0; o >>= 1) v = fmaxf(v, __shfl_xor_sync(0xffffffffu, v, o));
    return v;
}
__device__ __forceinline__ float warpSum(float v) {
    #pragma unroll
    for (int o = 16; o > 0; o >>= 1) v += __shfl_xor_sync(0xffffffffu, v, o);
    return v;
}

// ---------------------------------------------------------------------------
// Concat along features
// ---------------------------------------------------------------------------
__global__ void __launch_bounds__(256)
concat_kernel(const float* __restrict__ a, const float* __restrict__ b,
              float* __restrict__ o)
{
    size_t idx = (size_t)blockIdx.x * 256 + threadIdx.x;
    size_t r   = idx >> 8;
    int    c4  = (int)(idx & 255);
    float4 v;
    if (c4 < 128) v = reinterpret_cast<const float4*>(a)[r * 128 + c4];
    else          v = reinterpret_cast<const float4*>(b)[r * 128 + (c4 - 128)];
    reinterpret_cast<float4*>(o)[idx] = v;
}

// ---------------------------------------------------------------------------
// Row softmax over 2048 cols, in place
// ---------------------------------------------------------------------------
__global__ void __launch_bounds__(256)
softmax_kernel(float* __restrict__ S)
{
    float* p = S + (size_t)blockIdx.x * SEQ;
    const int tid  = threadIdx.x;
    const int lane = tid & 31;
    const int wid  = tid >> 5;
    __shared__ float sh[8];

    float v[8];
    *reinterpret_cast<float4*>(&v[0]) = *reinterpret_cast<const float4*>(&p[tid * 8]);
    *reinterpret_cast<float4*>(&v[4]) = *reinterpret_cast<const float4*>(&p[tid * 8 + 4]);

    float m = v[0];
    #pragma unroll
    for (int i = 1; i < 8; i++) m = fmaxf(m, v[i]);
    m = warpMax(m);
    if (lane == 0) sh[wid] = m;
    __syncthreads();
    m = sh[0];
    #pragma unroll
    for (int w = 1; w < 8; w++) m = fmaxf(m, sh[w]);
    __syncthreads();

    float s = 0.f;
    #pragma unroll
    for (int i = 0; i < 8; i++) { v[i] = expf(v[i] - m); s += v[i]; }
    s = warpSum(s);
    if (lane == 0) sh[wid] = s;
    __syncthreads();
    float tot = sh[0];
    #pragma unroll
    for (int w = 1; w < 8; w++) tot += sh[w];
    float inv = 1.f / tot;

    #pragma unroll
    for (int i = 0; i < 8; i++) v[i] *= inv;
    *reinterpret_cast<float4*>(&p[tid * 8])     = *reinterpret_cast<float4*>(&v[0]);
    *reinterpret_cast<float4*>(&p[tid * 8 + 4]) = *reinterpret_cast<float4*>(&v[4]);
}

// ---------------------------------------------------------------------------
// LayerNorm over last dim (512)
// ---------------------------------------------------------------------------
__global__ void __launch_bounds__(128)
layernorm_kernel(const float* __restrict__ in, float* __restrict__ out,
                 const float* __restrict__ gamma, const float* __restrict__ beta)
{
    const size_t base = (size_t)blockIdx.x * DIM;
    const int tid  = threadIdx.x;
    const int lane = tid & 31;
    const int wid  = tid >> 5;
    __shared__ float shs[4], shq[4];

    float4 x = *reinterpret_cast<const float4*>(&in[base + tid * 4]);
    float s  = x.x + x.y + x.z + x.w;
    float ss = x.x * x.x + x.y * x.y + x.z * x.z + x.w * x.w;
    s  = warpSum(s);
    ss = warpSum(ss);
    if (lane == 0) { shs[wid] = s; shq[wid] = ss; }
    __syncthreads();
    float sum = shs[0] + shs[1] + shs[2] + shs[3];
    float sq  = shq[0] + shq[1] + shq[2] + shq[3];
    float mu  = sum * (1.f / DIM);
    float var = sq * (1.f / DIM) - mu * mu;
    float rs  = rsqrtf(var + 1e-5f);

    float4 gm = *reinterpret_cast<const float4*>(&gamma[tid * 4]);
    float4 bt = *reinterpret_cast<const float4*>(&beta[tid * 4]);
    float4 o;
    o.x = (x.x - mu) * rs * gm.x + bt.x;
    o.y = (x.y - mu) * rs * gm.y + bt.y;
    o.z = (x.z - mu) * rs * gm.z + bt.z;
    o.w = (x.w - mu) * rs * gm.w + bt.w;
    *reinterpret_cast<float4*>(&out[base + tid * 4]) = o;
}

// ---------------------------------------------------------------------------
// Launch
// ---------------------------------------------------------------------------
extern "C" void kernel_launch(void* const* d_in, const int* in_sizes, int n_in,
                              void* d_out, int out_size)
{
    const float* Noise = (const float*)d_in[0];
    const float* X     = (const float*)d_in[1];
    const float* cond  = (const float*)d_in[2];
    const float* Wg    = (const float*)d_in[3];
    const float* bg    = (const float*)d_in[4];
    const float* W1    = (const float*)d_in[5];
    const float* b1    = (const float*)d_in[6];
    const float* W2    = (const float*)d_in[7];
    const float* b2    = (const float*)d_in[8];
    const float* g1    = (const float*)d_in[9];
    const float* be1   = (const float*)d_in[10];
    const float* g2    = (const float*)d_in[11];
    const float* be2   = (const float*)d_in[12];
    float* out = (float*)d_out;

    float *comb, *fused, *scores, *q, *h, *y;
    cudaGetSymbolAddress((void**)&comb,   g_comb);
    cudaGetSymbolAddress((void**)&fused,  g_fused);
    cudaGetSymbolAddress((void**)&scores, g_scores);
    cudaGetSymbolAddress((void**)&q,      g_q);
    cudaGetSymbolAddress((void**)&h,      g_h);
    cudaGetSymbolAddress((void**)&y,      g_y);

    const float scale = 0.04419417382415922f;  // 1/sqrt(512)

    // 1. combined = concat(Noise, cond)
    concat_kernel<<<NTOK, 256>>>(Noise, cond, comb);

    // 2. gate = sigmoid(comb @ Wg + bg); fused = gate*Noise + (1-gate)*cond
    gemm_mma<EPI_GATE, false><<<dim3(DIM / BN, NTOK / BM, 1), NTHREADS>>>(
        comb, Wg, fused,
        2 * DIM, 2 * DIM, DIM, DIM,
        0, 0, 0, bg, Noise, cond, 0.f);

    // 3. scores = fused @ X^T * scale  (batched NT)
    gemm_mma<EPI_SCALE, true><<<dim3(SEQ / BN, SEQ / BM, BATCH), NTHREADS>>>(
        fused, X, scores,
        DIM, DIM, DIM, SEQ,
        (size_t)SEQ * DIM, (size_t)SEQ * DIM, (size_t)SEQ * SEQ,
        nullptr, nullptr, nullptr, scale);

    // 4. softmax (in place)
    softmax_kernel<<<NTOK, 256>>>(scores);

    // 5. fused += attn @ X  (batched NN)
    gemm_mma<EPI_ADD, false><<<dim3(DIM / BN, SEQ / BM, BATCH), NTHREADS>>>(
        scores, X, fused,
        SEQ, SEQ, DIM, DIM,
        (size_t)SEQ * SEQ, (size_t)SEQ * DIM, (size_t)SEQ * DIM,
        nullptr, fused, nullptr, 0.f);

    // 6. q = LN1(fused)
    layernorm_kernel<<<NTOK, 128>>>(fused, q, g1, be1);

    // 7. h = gelu(q @ W1 + b1)
    gemm_mma<EPI_GELU, false><<<dim3(2 * DIM / BN, NTOK / BM, 1), NTHREADS>>>(
        q, W1, h,
        DIM, DIM, 2 * DIM, 2 * DIM,
        0, 0, 0, b1, nullptr, nullptr, 0.f);

    // 8. y = h @ W2 + b2 + q
    gemm_mma<EPI_BIAS_RES, false><<<dim3(DIM / BN, NTOK / BM, 1), NTHREADS>>>(
        h, W2, y,
        2 * DIM, 2 * DIM, DIM, DIM,
        0, 0, 0, b2, q, nullptr, 0.f);

    // 9. out = LN2(y)
    layernorm_kernel<<<NTOK, 128>>>(y, out, g2, be2);
}

// round 5
// speedup vs baseline: 3.0442x; 1.0700x over previous
#include <cuda_runtime.h>
#include <math.h>
#include <stdint.h>

// ---------------------------------------------------------------------------
// Problem constants
// ---------------------------------------------------------------------------
#define BATCH   8
#define SEQ     2048
#define DIM     512
#define NTOK    (BATCH * SEQ)          // 16384

// GEMM tiling (mma.sync m16n8k8 tf32)
#define BM 128
#define BN 128
#define BK 16
#define NTHREADS 256
#define STAGES 4

// smem pitches (floats)
#define PA 20      // [rows][k] K-contiguous pitch (128 rows x 16 k)
#define PBN 136    // [k][n]  N-contiguous pitch  (16 k x 128 n)
#define SBUFA 2560 // 128*20
#define SBUFB 2560 // max(128*20, 16*136)
#define STAGE_F (SBUFA + SBUFB)
#define SMEM_BYTES_G (STAGES * STAGE_F * 4)

// Epilogue tags
#define EPI_GATE     0
#define EPI_SCALE    1
#define EPI_ADD      2
#define EPI_GELU     3
#define EPI_BIAS_RES 4

// ---------------------------------------------------------------------------
// Scratch (device globals: allocation-free rule)
// ---------------------------------------------------------------------------
__device__ float g_fused [(size_t)NTOK * DIM];
__device__ float g_scores[(size_t)BATCH * SEQ * SEQ];
__device__ float g_q     [(size_t)NTOK * DIM];
__device__ float g_h     [(size_t)NTOK * 2 * DIM];
__device__ float g_y     [(size_t)NTOK * DIM];

// ---------------------------------------------------------------------------
// PTX helpers
// ---------------------------------------------------------------------------
__device__ __forceinline__ uint32_t smem_u32(const void* p) {
    uint32_t a;
    asm("{ .reg .u64 t; cvta.to.shared.u64 t, %1; cvt.u32.u64 %0, t; }" : "=r"(a) : "l"(p));
    return a;
}
__device__ __forceinline__ void cp16(uint32_t saddr, const void* gaddr) {
    asm volatile("cp.async.cg.shared.global [%0], [%1], 16;" :: "r"(saddr), "l"(gaddr));
}
__device__ __forceinline__ void cp_commit() {
    asm volatile("cp.async.commit_group;" ::: "memory");
}
template<int N>
__device__ __forceinline__ void cp_wait() {
    asm volatile("cp.async.wait_group %0;" :: "n"(N) : "memory");
}
__device__ __forceinline__ void mma_tf32(float* c, uint32_t a0, uint32_t a1,
                                         uint32_t a2, uint32_t a3,
                                         uint32_t b0, uint32_t b1) {
    asm volatile("mma.sync.aligned.m16n8k8.row.col.f32.tf32.tf32.f32 "
                 "{%0,%1,%2,%3}, {%4,%5,%6,%7}, {%8,%9}, {%0,%1,%2,%3};"
                 : "+f"(c[0]), "+f"(c[1]), "+f"(c[2]), "+f"(c[3])
                 : "r"(a0), "r"(a1), "r"(a2), "r"(a3), "r"(b0), "r"(b1));
}
__device__ __forceinline__ uint32_t ldsf(const float* p) {
    return __float_as_uint(*p);
}

// ---------------------------------------------------------------------------
// tf32 tensor-core GEMM: C[M,N] = A[M,K] * B  (B [N,K] if TB, [K,N] if !TB)
// 128x128x16 CTA tile, 8 warps (2x4), 64x32 warp tiles,
// 4-stage cp.async ring, 1 barrier per K-iter.
// If SPLITA: A columns [0,512) come from A, [512,1024) from A2 (virtual concat).
// ---------------------------------------------------------------------------
template<int EPI, bool TB, bool SPLITA>
__global__ void __launch_bounds__(NTHREADS)
gemm_mma(const float* __restrict__ A, const float* __restrict__ A2,
         const float* __restrict__ B,
         float* __restrict__ C,
         int K, int lda, int ldb, int ldc,
         size_t strA, size_t strB, size_t strC,
         const float* __restrict__ bias,
         const float* __restrict__ res0,
         const float* __restrict__ res1,
         float scale)
{
    extern __shared__ float dsm[];

    const int z = blockIdx.z;
    A += (size_t)z * strA;
    B += (size_t)z * strB;
    C += (size_t)z * strC;
    if (res0) res0 += (size_t)z * strC;
    if (res1) res1 += (size_t)z * strC;

    const int bm   = blockIdx.y * BM;
    const int bn   = blockIdx.x * BN;
    const int tid  = threadIdx.x;
    const int wid  = tid >> 5;
    const int lane = tid & 31;
    const int warp_m = wid & 1;        // 0..1 -> 64 rows
    const int warp_n = wid >> 1;       // 0..3 -> 32 cols
    const int g  = lane >> 2;          // 0..7
    const int tg = lane & 3;           // 0..3

    const uint32_t smB = smem_u32(dsm);

    float acc[4][4][4];
    #pragma unroll
    for (int i = 0; i < 4; i++)
        #pragma unroll
        for (int j = 0; j < 4; j++)
            #pragma unroll
            for (int e = 0; e < 4; e++) acc[i][j][e] = 0.f;

    const int nit = K / BK;

    // ---- prefetch: one K=16 tile into stage s ----
    auto prefetch = [&](int it) {
        const int kk = it * BK;
        const int st = it % STAGES;
        const uint32_t sa = smB + (uint32_t)(st * STAGE_F) * 4u;
        const uint32_t sb = sa + (uint32_t)SBUFA * 4u;
        #pragma unroll
        for (int t = 0; t < 2; t++) {
            int id = tid + t * NTHREADS;       // 0..511
            int r  = id >> 2;                  // 0..127
            int c4 = id & 3;
            int col = kk + c4 * 4;
            const float* src;
            if (SPLITA) {
                src = (col < DIM) ? (A  + (size_t)(bm + r) * DIM + col)
                                  : (A2 + (size_t)(bm + r) * DIM + (col - DIM));
            } else {
                src = A + (size_t)(bm + r) * lda + col;
            }
            cp16(sa + (uint32_t)(r * PA + c4 * 4) * 4u, src);
        }
        if (TB) {
            #pragma unroll
            for (int t = 0; t < 2; t++) {
                int id = tid + t * NTHREADS;
                int r  = id >> 2;              // n row 0..127
                int c4 = id & 3;
                cp16(sb + (uint32_t)(r * PA + c4 * 4) * 4u,
                     B + (size_t)(bn + r) * ldb + kk + c4 * 4);
            }
        } else {
            #pragma unroll
            for (int t = 0; t < 2; t++) {
                int id = tid + t * NTHREADS;
                int r  = id >> 5;              // k row 0..15
                int c4 = id & 31;
                cp16(sb + (uint32_t)(r * PBN + c4 * 4) * 4u,
                     B + (size_t)(kk + r) * ldb + bn + c4 * 4);
            }
        }
        cp_commit();
    };

    // prologue: fill 3 stages
    prefetch(0);
    prefetch(1);
    prefetch(2);

    #pragma unroll 1
    for (int it = 0; it < nit; it++) {
        cp_wait<2>();          // group 'it' complete (it+1, it+2 may be in flight)
        __syncthreads();       // all warps: data visible, previous compute done
        if (it + 3 < nit) prefetch(it + 3);   // writes stage (it-1)%4: safe

        const int st = it % STAGES;
        const float* Asb = dsm + st * STAGE_F;
        const float* Bsb = Asb + SBUFA;

        #pragma unroll
        for (int ks = 0; ks < 2; ks++) {
            const int kc = ks * 8;
            uint32_t af[4][4];
            #pragma unroll
            for (int mt = 0; mt < 4; mt++) {
                int m = warp_m * 64 + mt * 16;
                const float* ap = &Asb[(m + g) * PA + kc + tg];
                af[mt][0] = ldsf(ap);
                af[mt][1] = ldsf(ap + 8 * PA);
                af[mt][2] = ldsf(ap + 4);
                af[mt][3] = ldsf(ap + 8 * PA + 4);
            }
            uint32_t bf[4][2];
            #pragma unroll
            for (int nt = 0; nt < 4; nt++) {
                int n = warp_n * 32 + nt * 8;
                if (TB) {
                    const float* bp = &Bsb[(n + g) * PA + kc + tg];
                    bf[nt][0] = ldsf(bp);
                    bf[nt][1] = ldsf(bp + 4);
                } else {
                    const float* bp = &Bsb[(kc + tg) * PBN + n + g];
                    bf[nt][0] = ldsf(bp);
                    bf[nt][1] = ldsf(bp + 4 * PBN);
                }
            }
            #pragma unroll
            for (int mt = 0; mt < 4; mt++)
                #pragma unroll
                for (int nt = 0; nt < 4; nt++)
                    mma_tf32(acc[mt][nt], af[mt][0], af[mt][1], af[mt][2], af[mt][3],
                             bf[nt][0], bf[nt][1]);
        }
    }

    // ---- epilogue ----
    #pragma unroll
    for (int mt = 0; mt < 4; mt++) {
        #pragma unroll
        for (int nt = 0; nt < 4; nt++) {
            int r0 = bm + warp_m * 64 + mt * 16 + g;
            int cc = bn + warp_n * 32 + nt * 8 + tg * 2;
            #pragma unroll
            for (int half = 0; half < 2; half++) {
                int r = r0 + half * 8;
                float v0 = acc[mt][nt][half * 2 + 0];
                float v1 = acc[mt][nt][half * 2 + 1];
                size_t gix = (size_t)r * ldc + cc;
                float o0, o1;
                if (EPI == EPI_GATE) {
                    float gt0 = 1.f / (1.f + expf(-(v0 + bias[cc])));
                    float gt1 = 1.f / (1.f + expf(-(v1 + bias[cc + 1])));
                    o0 = gt0 * res0[gix]     + (1.f - gt0) * res1[gix];
                    o1 = gt1 * res0[gix + 1] + (1.f - gt1) * res1[gix + 1];
                } else if (EPI == EPI_SCALE) {
                    o0 = v0 * scale; o1 = v1 * scale;
                } else if (EPI == EPI_ADD) {
                    o0 = v0 + res0[gix]; o1 = v1 + res0[gix + 1];
                } else if (EPI == EPI_GELU) {
                    float x0 = v0 + bias[cc], x1 = v1 + bias[cc + 1];
                    o0 = 0.5f * x0 * (1.f + erff(x0 * 0.70710678118654752440f));
                    o1 = 0.5f * x1 * (1.f + erff(x1 * 0.70710678118654752440f));
                } else { // EPI_BIAS_RES
                    o0 = v0 + bias[cc]     + res0[gix];
                    o1 = v1 + bias[cc + 1] + res0[gix + 1];
                }
                *reinterpret_cast<float2*>(&C[gix]) = make_float2(o0, o1);
            }
        }
    }
}

// ---------------------------------------------------------------------------
// Warp helpers
// ---------------------------------------------------------------------------
__device__ __forceinline__ float warpMax(float v) {
    #pragma unroll
    for (int o = 16; o > 0; o >>= 1) v = fmaxf(v, __shfl_xor_sync(0xffffffffu, v, o));
    return v;
}
__device__ __forceinline__ float warpSum(float v) {
    #pragma unroll
    for (int o = 16; o > 0; o >>= 1) v += __shfl_xor_sync(0xffffffffu, v, o);
    return v;
}

// ---------------------------------------------------------------------------
// Row softmax over 2048 cols, in place
// ---------------------------------------------------------------------------
__global__ void __launch_bounds__(256)
softmax_kernel(float* __restrict__ S)
{
    float* p = S + (size_t)blockIdx.x * SEQ;
    const int tid  = threadIdx.x;
    const int lane = tid & 31;
    const int wid  = tid >> 5;
    __shared__ float sh[8];

    float v[8];
    *reinterpret_cast<float4*>(&v[0]) = *reinterpret_cast<const float4*>(&p[tid * 8]);
    *reinterpret_cast<float4*>(&v[4]) = *reinterpret_cast<const float4*>(&p[tid * 8 + 4]);

    float m = v[0];
    #pragma unroll
    for (int i = 1; i < 8; i++) m = fmaxf(m, v[i]);
    m = warpMax(m);
    if (lane == 0) sh[wid] = m;
    __syncthreads();
    m = sh[0];
    #pragma unroll
    for (int w = 1; w < 8; w++) m = fmaxf(m, sh[w]);
    __syncthreads();

    float s = 0.f;
    #pragma unroll
    for (int i = 0; i < 8; i++) { v[i] = expf(v[i] - m); s += v[i]; }
    s = warpSum(s);
    if (lane == 0) sh[wid] = s;
    __syncthreads();
    float tot = sh[0];
    #pragma unroll
    for (int w = 1; w < 8; w++) tot += sh[w];
    float inv = 1.f / tot;

    #pragma unroll
    for (int i = 0; i < 8; i++) v[i] *= inv;
    *reinterpret_cast<float4*>(&p[tid * 8])     = *reinterpret_cast<float4*>(&v[0]);
    *reinterpret_cast<float4*>(&p[tid * 8 + 4]) = *reinterpret_cast<float4*>(&v[4]);
}

// ---------------------------------------------------------------------------
// LayerNorm over last dim (512)
// ---------------------------------------------------------------------------
__global__ void __launch_bounds__(128)
layernorm_kernel(const float* __restrict__ in, float* __restrict__ out,
                 const float* __restrict__ gamma, const float* __restrict__ beta)
{
    const size_t base = (size_t)blockIdx.x * DIM;
    const int tid  = threadIdx.x;
    const int lane = tid & 31;
    const int wid  = tid >> 5;
    __shared__ float shs[4], shq[4];

    float4 x = *reinterpret_cast<const float4*>(&in[base + tid * 4]);
    float s  = x.x + x.y + x.z + x.w;
    float ss = x.x * x.x + x.y * x.y + x.z * x.z + x.w * x.w;
    s  = warpSum(s);
    ss = warpSum(ss);
    if (lane == 0) { shs[wid] = s; shq[wid] = ss; }
    __syncthreads();
    float sum = shs[0] + shs[1] + shs[2] + shs[3];
    float sq  = shq[0] + shq[1] + shq[2] + shq[3];
    float mu  = sum * (1.f / DIM);
    float var = sq * (1.f / DIM) - mu * mu;
    float rs  = rsqrtf(var + 1e-5f);

    float4 gm = *reinterpret_cast<const float4*>(&gamma[tid * 4]);
    float4 bt = *reinterpret_cast<const float4*>(&beta[tid * 4]);
    float4 o;
    o.x = (x.x - mu) * rs * gm.x + bt.x;
    o.y = (x.y - mu) * rs * gm.y + bt.y;
    o.z = (x.z - mu) * rs * gm.z + bt.z;
    o.w = (x.w - mu) * rs * gm.w + bt.w;
    *reinterpret_cast<float4*>(&out[base + tid * 4]) = o;
}

// ---------------------------------------------------------------------------
// Launch
// ---------------------------------------------------------------------------
extern "C" void kernel_launch(void* const* d_in, const int* in_sizes, int n_in,
                              void* d_out, int out_size)
{
    const float* Noise = (const float*)d_in[0];
    const float* X     = (const float*)d_in[1];
    const float* cond  = (const float*)d_in[2];
    const float* Wg    = (const float*)d_in[3];
    const float* bg    = (const float*)d_in[4];
    const float* W1    = (const float*)d_in[5];
    const float* b1    = (const float*)d_in[6];
    const float* W2    = (const float*)d_in[7];
    const float* b2    = (const float*)d_in[8];
    const float* g1    = (const float*)d_in[9];
    const float* be1   = (const float*)d_in[10];
    const float* g2    = (const float*)d_in[11];
    const float* be2   = (const float*)d_in[12];
    float* out = (float*)d_out;

    float *fused, *scores, *q, *h, *y;
    cudaGetSymbolAddress((void**)&fused,  g_fused);
    cudaGetSymbolAddress((void**)&scores, g_scores);
    cudaGetSymbolAddress((void**)&q,      g_q);
    cudaGetSymbolAddress((void**)&h,      g_h);
    cudaGetSymbolAddress((void**)&y,      g_y);

    cudaFuncSetAttribute(gemm_mma<EPI_GATE, false, true>,      cudaFuncAttributeMaxDynamicSharedMemorySize, SMEM_BYTES_G);
    cudaFuncSetAttribute(gemm_mma<EPI_SCALE, true, false>,     cudaFuncAttributeMaxDynamicSharedMemorySize, SMEM_BYTES_G);
    cudaFuncSetAttribute(gemm_mma<EPI_ADD, false, false>,      cudaFuncAttributeMaxDynamicSharedMemorySize, SMEM_BYTES_G);
    cudaFuncSetAttribute(gemm_mma<EPI_GELU, false, false>,     cudaFuncAttributeMaxDynamicSharedMemorySize, SMEM_BYTES_G);
    cudaFuncSetAttribute(gemm_mma<EPI_BIAS_RES, false, false>, cudaFuncAttributeMaxDynamicSharedMemorySize, SMEM_BYTES_G);

    const float scale = 0.04419417382415922f;  // 1/sqrt(512)

    // 1. gate = sigmoid(concat(Noise,cond) @ Wg + bg); fused = gate*Noise + (1-gate)*cond
    //    (concat folded into the GEMM A-operand read)
    gemm_mma<EPI_GATE, false, true><<<dim3(DIM / BN, NTOK / BM, 1), NTHREADS, SMEM_BYTES_G>>>(
        Noise, cond, Wg, fused,
        2 * DIM, 2 * DIM, DIM, DIM,
        0, 0, 0, bg, Noise, cond, 0.f);

    // 2. scores = fused @ X^T * scale  (batched NT)
    gemm_mma<EPI_SCALE, true, false><<<dim3(SEQ / BN, SEQ / BM, BATCH), NTHREADS, SMEM_BYTES_G>>>(
        fused, nullptr, X, scores,
        DIM, DIM, DIM, SEQ,
        (size_t)SEQ * DIM, (size_t)SEQ * DIM, (size_t)SEQ * SEQ,
        nullptr, nullptr, nullptr, scale);

    // 3. softmax (in place)
    softmax_kernel<<<NTOK, 256>>>(scores);

    // 4. fused += attn @ X  (batched NN)
    gemm_mma<EPI_ADD, false, false><<<dim3(DIM / BN, SEQ / BM, BATCH), NTHREADS, SMEM_BYTES_G>>>(
        scores, nullptr, X, fused,
        SEQ, SEQ, DIM, DIM,
        (size_t)SEQ * SEQ, (size_t)SEQ * DIM, (size_t)SEQ * DIM,
        nullptr, fused, nullptr, 0.f);

    // 5. q = LN1(fused)
    layernorm_kernel<<<NTOK, 128>>>(fused, q, g1, be1);

    // 6. h = gelu(q @ W1 + b1)
    gemm_mma<EPI_GELU, false, false><<<dim3(2 * DIM / BN, NTOK / BM, 1), NTHREADS, SMEM_BYTES_G>>>(
        q, nullptr, W1, h,
        DIM, DIM, 2 * DIM, 2 * DIM,
        0, 0, 0, b1, nullptr, nullptr, 0.f);

    // 7. y = h @ W2 + b2 + q
    gemm_mma<EPI_BIAS_RES, false, false><<<dim3(DIM / BN, NTOK / BM, 1), NTHREADS, SMEM_BYTES_G>>>(
        h, nullptr, W2, y,
        2 * DIM, 2 * DIM, DIM, DIM,
        0, 0, 0, b2, q, nullptr, 0.f);

    // 8. out = LN2(y)
    layernorm_kernel<<<NTOK, 128>>>(y, out, g2, be2);
}

// round 6
// speedup vs baseline: 3.3361x; 1.0959x over previous
#include <cuda_runtime.h>
#include <math.h>
#include <stdint.h>

// ---------------------------------------------------------------------------
// Problem constants
// ---------------------------------------------------------------------------
#define BATCH   8
#define SEQ     2048
#define DIM     512
#define NTOK    (BATCH * SEQ)          // 16384

// GEMM tiling (mma.sync m16n8k8 tf32)
#define BM 128
#define BN 128
#define BK 32
#define NTHREADS 256
#define STAGES 3

// smem pitches (floats)
#define PA 36      // [rows][k] K-contiguous pitch (128 rows x 32 k)
#define PBN 136    // [k][n]  N-contiguous pitch  (32 k x 128 n)
#define SBUFA 4608 // 128*36
#define SBUFB 4608 // max(128*36, 32*136=4352)
#define STAGE_F (SBUFA + SBUFB)
#define SMEM_BYTES_G (STAGES * STAGE_F * 4)

// Epilogue tags
#define EPI_GATE     0
#define EPI_SCALE    1
#define EPI_ADD      2
#define EPI_GELU     3
#define EPI_BIAS_RES 4

// ---------------------------------------------------------------------------
// Scratch (device globals: allocation-free rule)
// ---------------------------------------------------------------------------
__device__ float g_fused [(size_t)NTOK * DIM];
__device__ float g_scores[(size_t)BATCH * SEQ * SEQ];
__device__ float g_q     [(size_t)NTOK * DIM];
__device__ float g_h     [(size_t)NTOK * 2 * DIM];
__device__ float g_y     [(size_t)NTOK * DIM];

// ---------------------------------------------------------------------------
// PTX helpers
// ---------------------------------------------------------------------------
__device__ __forceinline__ uint32_t smem_u32(const void* p) {
    uint32_t a;
    asm("{ .reg .u64 t; cvta.to.shared.u64 t, %1; cvt.u32.u64 %0, t; }" : "=r"(a) : "l"(p));
    return a;
}
__device__ __forceinline__ void cp16(uint32_t saddr, const void* gaddr) {
    asm volatile("cp.async.cg.shared.global [%0], [%1], 16;" :: "r"(saddr), "l"(gaddr));
}
__device__ __forceinline__ void cp_commit() {
    asm volatile("cp.async.commit_group;" ::: "memory");
}
template<int N>
__device__ __forceinline__ void cp_wait() {
    asm volatile("cp.async.wait_group %0;" :: "n"(N) : "memory");
}
__device__ __forceinline__ void mma_tf32(float* c, uint32_t a0, uint32_t a1,
                                         uint32_t a2, uint32_t a3,
                                         uint32_t b0, uint32_t b1) {
    asm volatile("mma.sync.aligned.m16n8k8.row.col.f32.tf32.tf32.f32 "
                 "{%0,%1,%2,%3}, {%4,%5,%6,%7}, {%8,%9}, {%0,%1,%2,%3};"
                 : "+f"(c[0]), "+f"(c[1]), "+f"(c[2]), "+f"(c[3])
                 : "r"(a0), "r"(a1), "r"(a2), "r"(a3), "r"(b0), "r"(b1));
}
__device__ __forceinline__ uint32_t ldsf(const float* p) {
    return __float_as_uint(*p);
}

// ---------------------------------------------------------------------------
// tf32 tensor-core GEMM: C[M,N] = A[M,K] * B  (B [N,K] if TB, [K,N] if !TB)
// 128x128x32 CTA tile, 8 warps (2x4), 64x32 warp tiles,
// 3-stage cp.async ring, 1 barrier per K-iter (BK=32).
// If SPLITA: A columns [0,512) come from A, [512,1024) from A2 (virtual concat).
// ---------------------------------------------------------------------------
template<int EPI, bool TB, bool SPLITA>
__global__ void __launch_bounds__(NTHREADS, 2)
gemm_mma(const float* __restrict__ A, const float* __restrict__ A2,
         const float* __restrict__ B,
         float* __restrict__ C,
         int K, int lda, int ldb, int ldc,
         size_t strA, size_t strB, size_t strC,
         const float* __restrict__ bias,
         const float* __restrict__ res0,
         const float* __restrict__ res1,
         float scale)
{
    extern __shared__ float dsm[];

    const int z = blockIdx.z;
    A += (size_t)z * strA;
    B += (size_t)z * strB;
    C += (size_t)z * strC;
    if (res0) res0 += (size_t)z * strC;
    if (res1) res1 += (size_t)z * strC;

    const int bm   = blockIdx.y * BM;
    const int bn   = blockIdx.x * BN;
    const int tid  = threadIdx.x;
    const int wid  = tid >> 5;
    const int lane = tid & 31;
    const int warp_m = wid & 1;        // 0..1 -> 64 rows
    const int warp_n = wid >> 1;       // 0..3 -> 32 cols
    const int g  = lane >> 2;          // 0..7
    const int tg = lane & 3;           // 0..3

    const uint32_t smB = smem_u32(dsm);

    float acc[4][4][4];
    #pragma unroll
    for (int i = 0; i < 4; i++)
        #pragma unroll
        for (int j = 0; j < 4; j++)
            #pragma unroll
            for (int e = 0; e < 4; e++) acc[i][j][e] = 0.f;

    const int nit = K / BK;

    // ---- prefetch: one K=32 tile into stage it%STAGES ----
    auto prefetch = [&](int it) {
        const int kk = it * BK;
        const int st = it % STAGES;
        const uint32_t sa = smB + (uint32_t)(st * STAGE_F) * 4u;
        const uint32_t sb = sa + (uint32_t)SBUFA * 4u;
        #pragma unroll
        for (int t = 0; t < 4; t++) {
            int id = tid + t * NTHREADS;       // 0..1023
            int r  = id >> 3;                  // 0..127
            int c4 = id & 7;                   // 0..7 (float4)
            int col = kk + c4 * 4;
            const float* src;
            if (SPLITA) {
                src = (col < DIM) ? (A  + (size_t)(bm + r) * DIM + col)
                                  : (A2 + (size_t)(bm + r) * DIM + (col - DIM));
            } else {
                src = A + (size_t)(bm + r) * lda + col;
            }
            cp16(sa + (uint32_t)(r * PA + c4 * 4) * 4u, src);
        }
        if (TB) {
            #pragma unroll
            for (int t = 0; t < 4; t++) {
                int id = tid + t * NTHREADS;
                int r  = id >> 3;              // n row 0..127
                int c4 = id & 7;
                cp16(sb + (uint32_t)(r * PA + c4 * 4) * 4u,
                     B + (size_t)(bn + r) * ldb + kk + c4 * 4);
            }
        } else {
            #pragma unroll
            for (int t = 0; t < 4; t++) {
                int id = tid + t * NTHREADS;
                int r  = id >> 5;              // k row 0..31
                int c4 = id & 31;
                cp16(sb + (uint32_t)(r * PBN + c4 * 4) * 4u,
                     B + (size_t)(kk + r) * ldb + bn + c4 * 4);
            }
        }
        cp_commit();
    };

    // prologue: fill 2 stages
    prefetch(0);
    prefetch(1);

    #pragma unroll 1
    for (int it = 0; it < nit; it++) {
        cp_wait<1>();          // group 'it' complete (it+1 may be in flight)
        __syncthreads();       // all warps: data visible, stage (it-1) consumed
        if (it + 2 < nit) prefetch(it + 2);   // writes stage (it-1)%3: safe

        const int st = it % STAGES;
        const float* Asb = dsm + st * STAGE_F;
        const float* Bsb = Asb + SBUFA;

        #pragma unroll
        for (int ks = 0; ks < 4; ks++) {
            const int kc = ks * 8;
            uint32_t af[4][4];
            #pragma unroll
            for (int mt = 0; mt < 4; mt++) {
                int m = warp_m * 64 + mt * 16;
                const float* ap = &Asb[(m + g) * PA + kc + tg];
                af[mt][0] = ldsf(ap);
                af[mt][1] = ldsf(ap + 8 * PA);
                af[mt][2] = ldsf(ap + 4);
                af[mt][3] = ldsf(ap + 8 * PA + 4);
            }
            uint32_t bf[4][2];
            #pragma unroll
            for (int nt = 0; nt < 4; nt++) {
                int n = warp_n * 32 + nt * 8;
                if (TB) {
                    const float* bp = &Bsb[(n + g) * PA + kc + tg];
                    bf[nt][0] = ldsf(bp);
                    bf[nt][1] = ldsf(bp + 4);
                } else {
                    const float* bp = &Bsb[(kc + tg) * PBN + n + g];
                    bf[nt][0] = ldsf(bp);
                    bf[nt][1] = ldsf(bp + 4 * PBN);
                }
            }
            #pragma unroll
            for (int mt = 0; mt < 4; mt++)
                #pragma unroll
                for (int nt = 0; nt < 4; nt++)
                    mma_tf32(acc[mt][nt], af[mt][0], af[mt][1], af[mt][2], af[mt][3],
                             bf[nt][0], bf[nt][1]);
        }
    }

    // ---- epilogue ----
    #pragma unroll
    for (int mt = 0; mt < 4; mt++) {
        #pragma unroll
        for (int nt = 0; nt < 4; nt++) {
            int r0 = bm + warp_m * 64 + mt * 16 + g;
            int cc = bn + warp_n * 32 + nt * 8 + tg * 2;
            #pragma unroll
            for (int half = 0; half < 2; half++) {
                int r = r0 + half * 8;
                float v0 = acc[mt][nt][half * 2 + 0];
                float v1 = acc[mt][nt][half * 2 + 1];
                size_t gix = (size_t)r * ldc + cc;
                float o0, o1;
                if (EPI == EPI_GATE) {
                    float gt0 = 1.f / (1.f + expf(-(v0 + bias[cc])));
                    float gt1 = 1.f / (1.f + expf(-(v1 + bias[cc + 1])));
                    o0 = gt0 * res0[gix]     + (1.f - gt0) * res1[gix];
                    o1 = gt1 * res0[gix + 1] + (1.f - gt1) * res1[gix + 1];
                } else if (EPI == EPI_SCALE) {
                    o0 = v0 * scale; o1 = v1 * scale;
                } else if (EPI == EPI_ADD) {
                    o0 = v0 + res0[gix]; o1 = v1 + res0[gix + 1];
                } else if (EPI == EPI_GELU) {
                    float x0 = v0 + bias[cc], x1 = v1 + bias[cc + 1];
                    o0 = 0.5f * x0 * (1.f + erff(x0 * 0.70710678118654752440f));
                    o1 = 0.5f * x1 * (1.f + erff(x1 * 0.70710678118654752440f));
                } else { // EPI_BIAS_RES
                    o0 = v0 + bias[cc]     + res0[gix];
                    o1 = v1 + bias[cc + 1] + res0[gix + 1];
                }
                *reinterpret_cast<float2*>(&C[gix]) = make_float2(o0, o1);
            }
        }
    }
}

// ---------------------------------------------------------------------------
// Warp helpers
// ---------------------------------------------------------------------------
__device__ __forceinline__ float warpMax(float v) {
    #pragma unroll
    for (int o = 16; o > 0; o >>= 1) v = fmaxf(v, __shfl_xor_sync(0xffffffffu, v, o));
    return v;
}
__device__ __forceinline__ float warpSum(float v) {
    #pragma unroll
    for (int o = 16; o > 0; o >>= 1) v += __shfl_xor_sync(0xffffffffu, v, o);
    return v;
}

// ---------------------------------------------------------------------------
// Row softmax over 2048 cols, in place
// ---------------------------------------------------------------------------
__global__ void __launch_bounds__(256)
softmax_kernel(float* __restrict__ S)
{
    float* p = S + (size_t)blockIdx.x * SEQ;
    const int tid  = threadIdx.x;
    const int lane = tid & 31;
    const int wid  = tid >> 5;
    __shared__ float sh[8];

    float v[8];
    *reinterpret_cast<float4*>(&v[0]) = *reinterpret_cast<const float4*>(&p[tid * 8]);
    *reinterpret_cast<float4*>(&v[4]) = *reinterpret_cast<const float4*>(&p[tid * 8 + 4]);

    float m = v[0];
    #pragma unroll
    for (int i = 1; i < 8; i++) m = fmaxf(m, v[i]);
    m = warpMax(m);
    if (lane == 0) sh[wid] = m;
    __syncthreads();
    m = sh[0];
    #pragma unroll
    for (int w = 1; w < 8; w++) m = fmaxf(m, sh[w]);
    __syncthreads();

    float s = 0.f;
    #pragma unroll
    for (int i = 0; i < 8; i++) { v[i] = expf(v[i] - m); s += v[i]; }
    s = warpSum(s);
    if (lane == 0) sh[wid] = s;
    __syncthreads();
    float tot = sh[0];
    #pragma unroll
    for (int w = 1; w < 8; w++) tot += sh[w];
    float inv = 1.f / tot;

    #pragma unroll
    for (int i = 0; i < 8; i++) v[i] *= inv;
    *reinterpret_cast<float4*>(&p[tid * 8])     = *reinterpret_cast<float4*>(&v[0]);
    *reinterpret_cast<float4*>(&p[tid * 8 + 4]) = *reinterpret_cast<float4*>(&v[4]);
}

// ---------------------------------------------------------------------------
// LayerNorm over last dim (512)
// ---------------------------------------------------------------------------
__global__ void __launch_bounds__(128)
layernorm_kernel(const float* __restrict__ in, float* __restrict__ out,
                 const float* __restrict__ gamma, const float* __restrict__ beta)
{
    const size_t base = (size_t)blockIdx.x * DIM;
    const int tid  = threadIdx.x;
    const int lane = tid & 31;
    const int wid  = tid >> 5;
    __shared__ float shs[4], shq[4];

    float4 x = *reinterpret_cast<const float4*>(&in[base + tid * 4]);
    float s  = x.x + x.y + x.z + x.w;
    float ss = x.x * x.x + x.y * x.y + x.z * x.z + x.w * x.w;
    s  = warpSum(s);
    ss = warpSum(ss);
    if (lane == 0) { shs[wid] = s; shq[wid] = ss; }
    __syncthreads();
    float sum = shs[0] + shs[1] + shs[2] + shs[3];
    float sq  = shq[0] + shq[1] + shq[2] + shq[3];
    float mu  = sum * (1.f / DIM);
    float var = sq * (1.f / DIM) - mu * mu;
    float rs  = rsqrtf(var + 1e-5f);

    float4 gm = *reinterpret_cast<const float4*>(&gamma[tid * 4]);
    float4 bt = *reinterpret_cast<const float4*>(&beta[tid * 4]);
    float4 o;
    o.x = (x.x - mu) * rs * gm.x + bt.x;
    o.y = (x.y - mu) * rs * gm.y + bt.y;
    o.z = (x.z - mu) * rs * gm.z + bt.z;
    o.w = (x.w - mu) * rs * gm.w + bt.w;
    *reinterpret_cast<float4*>(&out[base + tid * 4]) = o;
}

// ---------------------------------------------------------------------------
// Launch
// ---------------------------------------------------------------------------
extern "C" void kernel_launch(void* const* d_in, const int* in_sizes, int n_in,
                              void* d_out, int out_size)
{
    const float* Noise = (const float*)d_in[0];
    const float* X     = (const float*)d_in[1];
    const float* cond  = (const float*)d_in[2];
    const float* Wg    = (const float*)d_in[3];
    const float* bg    = (const float*)d_in[4];
    const float* W1    = (const float*)d_in[5];
    const float* b1    = (const float*)d_in[6];
    const float* W2    = (const float*)d_in[7];
    const float* b2    = (const float*)d_in[8];
    const float* g1    = (const float*)d_in[9];
    const float* be1   = (const float*)d_in[10];
    const float* g2    = (const float*)d_in[11];
    const float* be2   = (const float*)d_in[12];
    float* out = (float*)d_out;

    float *fused, *scores, *q, *h, *y;
    cudaGetSymbolAddress((void**)&fused,  g_fused);
    cudaGetSymbolAddress((void**)&scores, g_scores);
    cudaGetSymbolAddress((void**)&q,      g_q);
    cudaGetSymbolAddress((void**)&h,      g_h);
    cudaGetSymbolAddress((void**)&y,      g_y);

    cudaFuncSetAttribute(gemm_mma<EPI_GATE, false, true>,      cudaFuncAttributeMaxDynamicSharedMemorySize, SMEM_BYTES_G);
    cudaFuncSetAttribute(gemm_mma<EPI_SCALE, true, false>,     cudaFuncAttributeMaxDynamicSharedMemorySize, SMEM_BYTES_G);
    cudaFuncSetAttribute(gemm_mma<EPI_ADD, false, false>,      cudaFuncAttributeMaxDynamicSharedMemorySize, SMEM_BYTES_G);
    cudaFuncSetAttribute(gemm_mma<EPI_GELU, false, false>,     cudaFuncAttributeMaxDynamicSharedMemorySize, SMEM_BYTES_G);
    cudaFuncSetAttribute(gemm_mma<EPI_BIAS_RES, false, false>, cudaFuncAttributeMaxDynamicSharedMemorySize, SMEM_BYTES_G);

    const float scale = 0.04419417382415922f;  // 1/sqrt(512)

    // 1. gate = sigmoid(concat(Noise,cond) @ Wg + bg); fused = gate*Noise + (1-gate)*cond
    gemm_mma<EPI_GATE, false, true><<<dim3(DIM / BN, NTOK / BM, 1), NTHREADS, SMEM_BYTES_G>>>(
        Noise, cond, Wg, fused,
        2 * DIM, 2 * DIM, DIM, DIM,
        0, 0, 0, bg, Noise, cond, 0.f);

    // 2. scores = fused @ X^T * scale  (batched NT)
    gemm_mma<EPI_SCALE, true, false><<<dim3(SEQ / BN, SEQ / BM, BATCH), NTHREADS, SMEM_BYTES_G>>>(
        fused, nullptr, X, scores,
        DIM, DIM, DIM, SEQ,
        (size_t)SEQ * DIM, (size_t)SEQ * DIM, (size_t)SEQ * SEQ,
        nullptr, nullptr, nullptr, scale);

    // 3. softmax (in place)
    softmax_kernel<<<NTOK, 256>>>(scores);

    // 4. fused += attn @ X  (batched NN)
    gemm_mma<EPI_ADD, false, false><<<dim3(DIM / BN, SEQ / BM, BATCH), NTHREADS, SMEM_BYTES_G>>>(
        scores, nullptr, X, fused,
        SEQ, SEQ, DIM, DIM,
        (size_t)SEQ * SEQ, (size_t)SEQ * DIM, (size_t)SEQ * DIM,
        nullptr, fused, nullptr, 0.f);

    // 5. q = LN1(fused)
    layernorm_kernel<<<NTOK, 128>>>(fused, q, g1, be1);

    // 6. h = gelu(q @ W1 + b1)
    gemm_mma<EPI_GELU, false, false><<<dim3(2 * DIM / BN, NTOK / BM, 1), NTHREADS, SMEM_BYTES_G>>>(
        q, nullptr, W1, h,
        DIM, DIM, 2 * DIM, 2 * DIM,
        0, 0, 0, b1, nullptr, nullptr, 0.f);

    // 7. y = h @ W2 + b2 + q
    gemm_mma<EPI_BIAS_RES, false, false><<<dim3(DIM / BN, NTOK / BM, 1), NTHREADS, SMEM_BYTES_G>>>(
        h, nullptr, W2, y,
        2 * DIM, 2 * DIM, DIM, DIM,
        0, 0, 0, b2, q, nullptr, 0.f);

    // 8. out = LN2(y)
    layernorm_kernel<<<NTOK, 128>>>(y, out, g2, be2);
}

// round 7
// speedup vs baseline: 3.3751x; 1.0117x over previous
#include <cuda_runtime.h>
#include <math.h>
#include <stdint.h>

// ---------------------------------------------------------------------------
// Problem constants
// ---------------------------------------------------------------------------
#define BATCH   8
#define SEQ     2048
#define DIM     512
#define NTOK    (BATCH * SEQ)          // 16384

// GEMM tiling (mma.sync m16n8k8 tf32)
#define BM 128
#define BN 128
#define BK 32
#define NTHREADS 128                   // 4 warps, 2x2, 64x64 warp tiles
#define STAGES 3

// smem pitches (floats)
#define PA 36      // [rows][k] K-contiguous pitch (128 rows x 32 k)
#define PBN 136    // [k][n]  N-contiguous pitch  (32 k x 128 n)
#define SBUFA 4608 // 128*36
#define SBUFB 4608 // max(128*36, 32*136=4352)
#define STAGE_F (SBUFA + SBUFB)
#define SMEM_BYTES_G (STAGES * STAGE_F * 4)

// Epilogue tags
#define EPI_GATE     0
#define EPI_SCALE    1
#define EPI_ADD      2
#define EPI_GELU     3
#define EPI_BIAS_RES 4

// ---------------------------------------------------------------------------
// Scratch (device globals: allocation-free rule)
// ---------------------------------------------------------------------------
__device__ float g_fused [(size_t)NTOK * DIM];
__device__ float g_scores[(size_t)BATCH * SEQ * SEQ];
__device__ float g_q     [(size_t)NTOK * DIM];
__device__ float g_h     [(size_t)NTOK * 2 * DIM];
__device__ float g_y     [(size_t)NTOK * DIM];

// ---------------------------------------------------------------------------
// PTX helpers
// ---------------------------------------------------------------------------
__device__ __forceinline__ uint32_t smem_u32(const void* p) {
    uint32_t a;
    asm("{ .reg .u64 t; cvta.to.shared.u64 t, %1; cvt.u32.u64 %0, t; }" : "=r"(a) : "l"(p));
    return a;
}
__device__ __forceinline__ void cp16(uint32_t saddr, const void* gaddr) {
    asm volatile("cp.async.cg.shared.global [%0], [%1], 16;" :: "r"(saddr), "l"(gaddr));
}
__device__ __forceinline__ void cp_commit() {
    asm volatile("cp.async.commit_group;" ::: "memory");
}
template<int N>
__device__ __forceinline__ void cp_wait() {
    asm volatile("cp.async.wait_group %0;" :: "n"(N) : "memory");
}
__device__ __forceinline__ void mma_tf32(float* c, uint32_t a0, uint32_t a1,
                                         uint32_t a2, uint32_t a3,
                                         uint32_t b0, uint32_t b1) {
    asm volatile("mma.sync.aligned.m16n8k8.row.col.f32.tf32.tf32.f32 "
                 "{%0,%1,%2,%3}, {%4,%5,%6,%7}, {%8,%9}, {%0,%1,%2,%3};"
                 : "+f"(c[0]), "+f"(c[1]), "+f"(c[2]), "+f"(c[3])
                 : "r"(a0), "r"(a1), "r"(a2), "r"(a3), "r"(b0), "r"(b1));
}
__device__ __forceinline__ uint32_t ldsf(const float* p) {
    return __float_as_uint(*p);
}

// ---------------------------------------------------------------------------
// tf32 tensor-core GEMM: C[M,N] = A[M,K] * B  (B [N,K] if TB, [K,N] if !TB)
// 128x128x32 CTA tile, 4 warps (2x2), 64x64 warp tiles,
// 3-stage cp.async ring, 1 barrier per K-iter.
// If SPLITA: A columns [0,512) come from A, [512,1024) from A2 (virtual concat).
// ---------------------------------------------------------------------------
template<int EPI, bool TB, bool SPLITA>
__global__ void __launch_bounds__(NTHREADS, 2)
gemm_mma(const float* __restrict__ A, const float* __restrict__ A2,
         const float* __restrict__ B,
         float* __restrict__ C,
         int K, int lda, int ldb, int ldc,
         size_t strA, size_t strB, size_t strC,
         const float* __restrict__ bias,
         const float* __restrict__ res0,
         const float* __restrict__ res1,
         float scale)
{
    extern __shared__ float dsm[];

    const int z = blockIdx.z;
    A += (size_t)z * strA;
    B += (size_t)z * strB;
    C += (size_t)z * strC;
    if (res0) res0 += (size_t)z * strC;
    if (res1) res1 += (size_t)z * strC;

    const int bm   = blockIdx.y * BM;
    const int bn   = blockIdx.x * BN;
    const int tid  = threadIdx.x;
    const int wid  = tid >> 5;
    const int lane = tid & 31;
    const int warp_m = wid & 1;        // 0..1 -> 64 rows
    const int warp_n = wid >> 1;       // 0..1 -> 64 cols
    const int g  = lane >> 2;          // 0..7
    const int tg = lane & 3;           // 0..3

    const uint32_t smB = smem_u32(dsm);

    float acc[4][8][4];
    #pragma unroll
    for (int i = 0; i < 4; i++)
        #pragma unroll
        for (int j = 0; j < 8; j++)
            #pragma unroll
            for (int e = 0; e < 4; e++) acc[i][j][e] = 0.f;

    const int nit = K / BK;

    // ---- prefetch: one K=32 tile into stage it%STAGES ----
    auto prefetch = [&](int it) {
        const int kk = it * BK;
        const int st = it % STAGES;
        const uint32_t sa = smB + (uint32_t)(st * STAGE_F) * 4u;
        const uint32_t sb = sa + (uint32_t)SBUFA * 4u;
        #pragma unroll
        for (int t = 0; t < 8; t++) {
            int id = tid + t * NTHREADS;       // 0..1023
            int r  = id >> 3;                  // 0..127
            int c4 = id & 7;                   // 0..7 (float4)
            int col = kk + c4 * 4;
            const float* src;
            if (SPLITA) {
                src = (col < DIM) ? (A  + (size_t)(bm + r) * DIM + col)
                                  : (A2 + (size_t)(bm + r) * DIM + (col - DIM));
            } else {
                src = A + (size_t)(bm + r) * lda + col;
            }
            cp16(sa + (uint32_t)(r * PA + c4 * 4) * 4u, src);
        }
        if (TB) {
            #pragma unroll
            for (int t = 0; t < 8; t++) {
                int id = tid + t * NTHREADS;
                int r  = id >> 3;              // n row 0..127
                int c4 = id & 7;
                cp16(sb + (uint32_t)(r * PA + c4 * 4) * 4u,
                     B + (size_t)(bn + r) * ldb + kk + c4 * 4);
            }
        } else {
            #pragma unroll
            for (int t = 0; t < 8; t++) {
                int id = tid + t * NTHREADS;
                int r  = id >> 5;              // k row 0..31
                int c4 = id & 31;
                cp16(sb + (uint32_t)(r * PBN + c4 * 4) * 4u,
                     B + (size_t)(kk + r) * ldb + bn + c4 * 4);
            }
        }
        cp_commit();
    };

    // prologue: fill 2 stages
    prefetch(0);
    prefetch(1);

    #pragma unroll 1
    for (int it = 0; it < nit; it++) {
        cp_wait<1>();          // group 'it' complete (it+1 may be in flight)
        __syncthreads();       // data visible; stage (it-1) fully consumed
        if (it + 2 < nit) prefetch(it + 2);   // writes stage (it-1)%3: safe

        const int st = it % STAGES;
        const float* Asb = dsm + st * STAGE_F;
        const float* Bsb = Asb + SBUFA;

        #pragma unroll
        for (int ks = 0; ks < 4; ks++) {
            const int kc = ks * 8;
            uint32_t af[4][4];
            #pragma unroll
            for (int mt = 0; mt < 4; mt++) {
                int m = warp_m * 64 + mt * 16;
                const float* ap = &Asb[(m + g) * PA + kc + tg];
                af[mt][0] = ldsf(ap);
                af[mt][1] = ldsf(ap + 8 * PA);
                af[mt][2] = ldsf(ap + 4);
                af[mt][3] = ldsf(ap + 8 * PA + 4);
            }
            uint32_t bf[8][2];
            #pragma unroll
            for (int nt = 0; nt < 8; nt++) {
                int n = warp_n * 64 + nt * 8;
                if (TB) {
                    const float* bp = &Bsb[(n + g) * PA + kc + tg];
                    bf[nt][0] = ldsf(bp);
                    bf[nt][1] = ldsf(bp + 4);
                } else {
                    const float* bp = &Bsb[(kc + tg) * PBN + n + g];
                    bf[nt][0] = ldsf(bp);
                    bf[nt][1] = ldsf(bp + 4 * PBN);
                }
            }
            #pragma unroll
            for (int mt = 0; mt < 4; mt++)
                #pragma unroll
                for (int nt = 0; nt < 8; nt++)
                    mma_tf32(acc[mt][nt], af[mt][0], af[mt][1], af[mt][2], af[mt][3],
                             bf[nt][0], bf[nt][1]);
        }
    }

    // ---- epilogue ----
    #pragma unroll
    for (int mt = 0; mt < 4; mt++) {
        #pragma unroll
        for (int nt = 0; nt < 8; nt++) {
            int r0 = bm + warp_m * 64 + mt * 16 + g;
            int cc = bn + warp_n * 64 + nt * 8 + tg * 2;
            #pragma unroll
            for (int half = 0; half < 2; half++) {
                int r = r0 + half * 8;
                float v0 = acc[mt][nt][half * 2 + 0];
                float v1 = acc[mt][nt][half * 2 + 1];
                size_t gix = (size_t)r * ldc + cc;
                float o0, o1;
                if (EPI == EPI_GATE) {
                    float gt0 = 1.f / (1.f + expf(-(v0 + bias[cc])));
                    float gt1 = 1.f / (1.f + expf(-(v1 + bias[cc + 1])));
                    o0 = gt0 * res0[gix]     + (1.f - gt0) * res1[gix];
                    o1 = gt1 * res0[gix + 1] + (1.f - gt1) * res1[gix + 1];
                } else if (EPI == EPI_SCALE) {
                    o0 = v0 * scale; o1 = v1 * scale;
                } else if (EPI == EPI_ADD) {
                    o0 = v0 + res0[gix]; o1 = v1 + res0[gix + 1];
                } else if (EPI == EPI_GELU) {
                    float x0 = v0 + bias[cc], x1 = v1 + bias[cc + 1];
                    o0 = 0.5f * x0 * (1.f + erff(x0 * 0.70710678118654752440f));
                    o1 = 0.5f * x1 * (1.f + erff(x1 * 0.70710678118654752440f));
                } else { // EPI_BIAS_RES
                    o0 = v0 + bias[cc]     + res0[gix];
                    o1 = v1 + bias[cc + 1] + res0[gix + 1];
                }
                *reinterpret_cast<float2*>(&C[gix]) = make_float2(o0, o1);
            }
        }
    }
}

// ---------------------------------------------------------------------------
// Warp helpers
// ---------------------------------------------------------------------------
__device__ __forceinline__ float warpMax(float v) {
    #pragma unroll
    for (int o = 16; o > 0; o >>= 1) v = fmaxf(v, __shfl_xor_sync(0xffffffffu, v, o));
    return v;
}
__device__ __forceinline__ float warpSum(float v) {
    #pragma unroll
    for (int o = 16; o > 0; o >>= 1) v += __shfl_xor_sync(0xffffffffu, v, o);
    return v;
}

// ---------------------------------------------------------------------------
// Row softmax over 2048 cols, in place
// ---------------------------------------------------------------------------
__global__ void __launch_bounds__(256)
softmax_kernel(float* __restrict__ S)
{
    float* p = S + (size_t)blockIdx.x * SEQ;
    const int tid  = threadIdx.x;
    const int lane = tid & 31;
    const int wid  = tid >> 5;
    __shared__ float sh[8];

    float v[8];
    *reinterpret_cast<float4*>(&v[0]) = *reinterpret_cast<const float4*>(&p[tid * 8]);
    *reinterpret_cast<float4*>(&v[4]) = *reinterpret_cast<const float4*>(&p[tid * 8 + 4]);

    float m = v[0];
    #pragma unroll
    for (int i = 1; i < 8; i++) m = fmaxf(m, v[i]);
    m = warpMax(m);
    if (lane == 0) sh[wid] = m;
    __syncthreads();
    m = sh[0];
    #pragma unroll
    for (int w = 1; w < 8; w++) m = fmaxf(m, sh[w]);
    __syncthreads();

    float s = 0.f;
    #pragma unroll
    for (int i = 0; i < 8; i++) { v[i] = expf(v[i] - m); s += v[i]; }
    s = warpSum(s);
    if (lane == 0) sh[wid] = s;
    __syncthreads();
    float tot = sh[0];
    #pragma unroll
    for (int w = 1; w < 8; w++) tot += sh[w];
    float inv = 1.f / tot;

    #pragma unroll
    for (int i = 0; i < 8; i++) v[i] *= inv;
    *reinterpret_cast<float4*>(&p[tid * 8])     = *reinterpret_cast<float4*>(&v[0]);
    *reinterpret_cast<float4*>(&p[tid * 8 + 4]) = *reinterpret_cast<float4*>(&v[4]);
}

// ---------------------------------------------------------------------------
// LayerNorm over last dim (512)
// ---------------------------------------------------------------------------
__global__ void __launch_bounds__(128)
layernorm_kernel(const float* __restrict__ in, float* __restrict__ out,
                 const float* __restrict__ gamma, const float* __restrict__ beta)
{
    const size_t base = (size_t)blockIdx.x * DIM;
    const int tid  = threadIdx.x;
    const int lane = tid & 31;
    const int wid  = tid >> 5;
    __shared__ float shs[4], shq[4];

    float4 x = *reinterpret_cast<const float4*>(&in[base + tid * 4]);
    float s  = x.x + x.y + x.z + x.w;
    float ss = x.x * x.x + x.y * x.y + x.z * x.z + x.w * x.w;
    s  = warpSum(s);
    ss = warpSum(ss);
    if (lane == 0) { shs[wid] = s; shq[wid] = ss; }
    __syncthreads();
    float sum = shs[0] + shs[1] + shs[2] + shs[3];
    float sq  = shq[0] + shq[1] + shq[2] + shq[3];
    float mu  = sum * (1.f / DIM);
    float var = sq * (1.f / DIM) - mu * mu;
    float rs  = rsqrtf(var + 1e-5f);

    float4 gm = *reinterpret_cast<const float4*>(&gamma[tid * 4]);
    float4 bt = *reinterpret_cast<const float4*>(&beta[tid * 4]);
    float4 o;
    o.x = (x.x - mu) * rs * gm.x + bt.x;
    o.y = (x.y - mu) * rs * gm.y + bt.y;
    o.z = (x.z - mu) * rs * gm.z + bt.z;
    o.w = (x.w - mu) * rs * gm.w + bt.w;
    *reinterpret_cast<float4*>(&out[base + tid * 4]) = o;
}

// ---------------------------------------------------------------------------
// Launch
// ---------------------------------------------------------------------------
extern "C" void kernel_launch(void* const* d_in, const int* in_sizes, int n_in,
                              void* d_out, int out_size)
{
    const float* Noise = (const float*)d_in[0];
    const float* X     = (const float*)d_in[1];
    const float* cond  = (const float*)d_in[2];
    const float* Wg    = (const float*)d_in[3];
    const float* bg    = (const float*)d_in[4];
    const float* W1    = (const float*)d_in[5];
    const float* b1    = (const float*)d_in[6];
    const float* W2    = (const float*)d_in[7];
    const float* b2    = (const float*)d_in[8];
    const float* g1    = (const float*)d_in[9];
    const float* be1   = (const float*)d_in[10];
    const float* g2    = (const float*)d_in[11];
    const float* be2   = (const float*)d_in[12];
    float* out = (float*)d_out;

    float *fused, *scores, *q, *h, *y;
    cudaGetSymbolAddress((void**)&fused,  g_fused);
    cudaGetSymbolAddress((void**)&scores, g_scores);
    cudaGetSymbolAddress((void**)&q,      g_q);
    cudaGetSymbolAddress((void**)&h,      g_h);
    cudaGetSymbolAddress((void**)&y,      g_y);

    cudaFuncSetAttribute(gemm_mma<EPI_GATE, false, true>,      cudaFuncAttributeMaxDynamicSharedMemorySize, SMEM_BYTES_G);
    cudaFuncSetAttribute(gemm_mma<EPI_SCALE, true, false>,     cudaFuncAttributeMaxDynamicSharedMemorySize, SMEM_BYTES_G);
    cudaFuncSetAttribute(gemm_mma<EPI_ADD, false, false>,      cudaFuncAttributeMaxDynamicSharedMemorySize, SMEM_BYTES_G);
    cudaFuncSetAttribute(gemm_mma<EPI_GELU, false, false>,     cudaFuncAttributeMaxDynamicSharedMemorySize, SMEM_BYTES_G);
    cudaFuncSetAttribute(gemm_mma<EPI_BIAS_RES, false, false>, cudaFuncAttributeMaxDynamicSharedMemorySize, SMEM_BYTES_G);

    const float scale = 0.04419417382415922f;  // 1/sqrt(512)

    // 1. gate = sigmoid(concat(Noise,cond) @ Wg + bg); fused = gate*Noise + (1-gate)*cond
    gemm_mma<EPI_GATE, false, true><<<dim3(DIM / BN, NTOK / BM, 1), NTHREADS, SMEM_BYTES_G>>>(
        Noise, cond, Wg, fused,
        2 * DIM, 2 * DIM, DIM, DIM,
        0, 0, 0, bg, Noise, cond, 0.f);

    // 2. scores = fused @ X^T * scale  (batched NT)
    gemm_mma<EPI_SCALE, true, false><<<dim3(SEQ / BN, SEQ / BM, BATCH), NTHREADS, SMEM_BYTES_G>>>(
        fused, nullptr, X, scores,
        DIM, DIM, DIM, SEQ,
        (size_t)SEQ * DIM, (size_t)SEQ * DIM, (size_t)SEQ * SEQ,
        nullptr, nullptr, nullptr, scale);

    // 3. softmax (in place)
    softmax_kernel<<<NTOK, 256>>>(scores);

    // 4. fused += attn @ X  (batched NN)
    gemm_mma<EPI_ADD, false, false><<<dim3(DIM / BN, SEQ / BM, BATCH), NTHREADS, SMEM_BYTES_G>>>(
        scores, nullptr, X, fused,
        SEQ, SEQ, DIM, DIM,
        (size_t)SEQ * SEQ, (size_t)SEQ * DIM, (size_t)SEQ * DIM,
        nullptr, fused, nullptr, 0.f);

    // 5. q = LN1(fused)
    layernorm_kernel<<<NTOK, 128>>>(fused, q, g1, be1);

    // 6. h = gelu(q @ W1 + b1)
    gemm_mma<EPI_GELU, false, false><<<dim3(2 * DIM / BN, NTOK / BM, 1), NTHREADS, SMEM_BYTES_G>>>(
        q, nullptr, W1, h,
        DIM, DIM, 2 * DIM, 2 * DIM,
        0, 0, 0, b1, nullptr, nullptr, 0.f);

    // 7. y = h @ W2 + b2 + q
    gemm_mma<EPI_BIAS_RES, false, false><<<dim3(DIM / BN, NTOK / BM, 1), NTHREADS, SMEM_BYTES_G>>>(
        h, nullptr, W2, y,
        2 * DIM, 2 * DIM, DIM, DIM,
        0, 0, 0, b2, q, nullptr, 0.f);

    // 8. out = LN2(y)
    layernorm_kernel<<<NTOK, 128>>>(y, out, g2, be2);
}